// round 17
// baseline (speedup 1.0000x reference)
#include <cuda_runtime.h>
#include <cstdint>
#include <cstddef>

#define Bb   64
#define Nn   512
#define CINc 128
#define Hh   256
#define OUTd 12
#define Ee   8192
#define G3   768
#define BN   (Bb*Nn)

// ------------------------- device scratch (no allocs) -----------------------
__device__ float g_xwz[BN*Hh], g_xwh[BN*Hh], g_cz[BN*Hh], g_ch[BN*Hh];
__device__ float g_zlin[BN*Hh], g_hlin[BN*Hh];
__device__ float g_gi[(size_t)Nn*G3*Bb];
__device__ float g_h1[(size_t)Nn*Bb*Hh], g_h2[(size_t)Nn*Bb*Hh];
__device__ float g_deg[Nn], g_dinv[Nn], g_selfnorm[Nn];
__device__ int   g_cnt[Nn], g_rowptr[Nn+1], g_fillpos[Nn];
__device__ int   g_csr_src[Ee];
__device__ float g_csr_norm[Ee];
__device__ unsigned g_flags[8 * Nn];          // [cluster][step] arrival counts

// ------------------------- helpers ------------------------------------------
__device__ __forceinline__ float sigf(float x) { return 1.0f / (1.0f + expf(-x)); }

__device__ __forceinline__ void fma2(uint64_t& d, uint64_t a, uint64_t b) {
    asm("fma.rn.f32x2 %0, %1, %2, %0;" : "+l"(d) : "l"(a), "l"(b));
}
__device__ __forceinline__ uint64_t dup2(float a) {
    uint64_t d; asm("mov.b64 %0, {%1, %1};" : "=l"(d) : "f"(a)); return d;
}
__device__ __forceinline__ float2 unp2(uint64_t v) {
    float2 f; asm("mov.b64 {%0, %1}, %2;" : "=f"(f.x), "=f"(f.y) : "l"(v)); return f;
}
__device__ __forceinline__ uint32_t smem_u32(const void* p) {
    uint32_t a;
    asm("{ .reg .u64 t; cvta.to.shared.u64 t, %1; cvt.u32.u64 %0, t; }"
        : "=r"(a) : "l"(p));
    return a;
}
__device__ __forceinline__ uint32_t ctarank() {
    uint32_t r;
    asm("mov.u32 %0, %%cluster_ctarank;" : "=r"(r));
    return r;
}
__device__ __forceinline__ void st_cluster_f32(uint32_t local_addr, int peer, float v) {
    uint32_t ra;
    asm volatile("mapa.shared::cluster.u32 %0, %1, %2;" : "=r"(ra) : "r"(local_addr), "r"(peer));
    asm volatile("st.shared::cluster.f32 [%0], %1;" :: "r"(ra), "f"(v) : "memory");
}
__device__ __forceinline__ void cluster_arrive_() {
    asm volatile("barrier.cluster.arrive.aligned;" ::: "memory");
}
__device__ __forceinline__ void cluster_wait_() {
    asm volatile("barrier.cluster.wait.aligned;" ::: "memory");
}

// ------------------------- edge preprocessing -------------------------------
__global__ void prep_init() {
    int t = threadIdx.x;
    if (t < Nn) { g_deg[t] = 2.0f; g_cnt[t] = 0; }
}
__global__ void prep_count(const int* __restrict__ ei, const float* __restrict__ ew) {
    int e = blockIdx.x * 256 + threadIdx.x;
    if (e >= Ee) return;
    int tgt = ei[Ee + e];
    atomicAdd(&g_deg[tgt], ew[e]);
    atomicAdd(&g_cnt[tgt], 1);
}
__global__ void prep_scan() {
    __shared__ int s[Nn];
    int t = threadIdx.x;
    float d = g_deg[t];
    float di = (d > 0.f) ? rsqrtf(d) : 0.f;
    g_dinv[t] = di;
    g_selfnorm[t] = 2.0f * di * di;
    s[t] = g_cnt[t];
    __syncthreads();
    for (int off = 1; off < Nn; off <<= 1) {
        int v = (t >= off) ? s[t - off] : 0;
        __syncthreads();
        s[t] += v;
        __syncthreads();
    }
    g_rowptr[t + 1] = s[t];
    if (t == 0) g_rowptr[0] = 0;
    g_fillpos[t] = s[t] - g_cnt[t];
}
__global__ void prep_fill(const int* __restrict__ ei, const float* __restrict__ ew) {
    int e = blockIdx.x * 256 + threadIdx.x;
    if (e >= Ee) return;
    int src = ei[e], tgt = ei[Ee + e];
    int pos = atomicAdd(&g_fillpos[tgt], 1);
    g_csr_src[pos]  = src;
    g_csr_norm[pos] = g_dinv[src] * ew[e] * g_dinv[tgt];
}

// ------------------------- tiled SGEMM (f32x2) ------------------------------
__global__ void sgemm64(const float* __restrict__ A, const float* __restrict__ Bm,
                        const float* __restrict__ bias, float* __restrict__ C,
                        int M, int K, int Nc) {
    __shared__ __align__(16) float As[16][68];
    __shared__ __align__(16) float Bs[16][68];
    int m0 = blockIdx.x * 64, n0 = blockIdx.y * 64;
    int tid = threadIdx.x;
    int tx = tid & 15, ty = tid >> 4;
    uint64_t acc[4][2] = {};
    for (int k0 = 0; k0 < K; k0 += 16) {
        #pragma unroll
        for (int i = 0; i < 4; i++) {
            int idx = tid + i * 256;
            int m = idx >> 4, k = idx & 15;
            As[k][m] = A[(size_t)(m0 + m) * K + k0 + k];
        }
        #pragma unroll
        for (int i = 0; i < 4; i++) {
            int idx = tid + i * 256;
            int k = idx >> 6, n = idx & 63;
            Bs[k][n] = Bm[(size_t)(k0 + k) * Nc + n0 + n];
        }
        __syncthreads();
        #pragma unroll
        for (int k = 0; k < 16; k++) {
            float4 av = *(const float4*)&As[k][ty * 4];
            ulonglong2 bv = *(const ulonglong2*)&Bs[k][tx * 4];
            uint64_t a0 = dup2(av.x), a1 = dup2(av.y);
            uint64_t a2 = dup2(av.z), a3 = dup2(av.w);
            fma2(acc[0][0], a0, bv.x); fma2(acc[0][1], a0, bv.y);
            fma2(acc[1][0], a1, bv.x); fma2(acc[1][1], a1, bv.y);
            fma2(acc[2][0], a2, bv.x); fma2(acc[2][1], a2, bv.y);
            fma2(acc[3][0], a3, bv.x); fma2(acc[3][1], a3, bv.y);
        }
        __syncthreads();
    }
    float bj[4];
    #pragma unroll
    for (int j = 0; j < 4; j++) bj[j] = bias ? bias[n0 + tx * 4 + j] : 0.f;
    #pragma unroll
    for (int i = 0; i < 4; i++) {
        int m = m0 + ty * 4 + i;
        float2 c01 = unp2(acc[i][0]), c23 = unp2(acc[i][1]);
        float cv[4] = {c01.x, c01.y, c23.x, c23.y};
        #pragma unroll
        for (int j = 0; j < 4; j++)
            C[(size_t)m * Nc + n0 + tx * 4 + j] = cv[j] + bj[j];
    }
}

// ------------------------- gi GEMM (layer 0 input projections) --------------
__global__ void gi_gemm(const float* __restrict__ Xbase, int strideB, int strideN,
                        const float* __restrict__ W, const float* __restrict__ bih,
                        int K) {
    __shared__ __align__(16) float Xs[16][68];
    __shared__ __align__(16) float Ws[16][68];
    int n  = blockIdx.x;
    int o0 = blockIdx.y * 64;
    int tid = threadIdx.x;
    int tb = tid & 15, to = tid >> 4;
    uint64_t acc[4][2] = {};
    for (int k0 = 0; k0 < K; k0 += 16) {
        #pragma unroll
        for (int i = 0; i < 4; i++) {
            int idx = tid + i * 256;
            int b = idx >> 4, k = idx & 15;
            Xs[k][b] = Xbase[(size_t)b * strideB + (size_t)n * strideN + k0 + k];
        }
        #pragma unroll
        for (int i = 0; i < 4; i++) {
            int idx = tid + i * 256;
            int o = idx >> 4, k = idx & 15;
            Ws[k][o] = W[(size_t)(o0 + o) * K + k0 + k];
        }
        __syncthreads();
        #pragma unroll
        for (int k = 0; k < 16; k++) {
            float4 wv = *(const float4*)&Ws[k][to * 4];
            ulonglong2 xv = *(const ulonglong2*)&Xs[k][tb * 4];
            uint64_t w0 = dup2(wv.x), w1 = dup2(wv.y);
            uint64_t w2 = dup2(wv.z), w3 = dup2(wv.w);
            fma2(acc[0][0], w0, xv.x); fma2(acc[0][1], w0, xv.y);
            fma2(acc[1][0], w1, xv.x); fma2(acc[1][1], w1, xv.y);
            fma2(acc[2][0], w2, xv.x); fma2(acc[2][1], w2, xv.y);
            fma2(acc[3][0], w3, xv.x); fma2(acc[3][1], w3, xv.y);
        }
        __syncthreads();
    }
    size_t base = (size_t)n * G3 * Bb;
    #pragma unroll
    for (int i = 0; i < 4; i++) {
        int o = o0 + to * 4 + i;
        float bv = bih[o];
        float2 c01 = unp2(acc[i][0]), c23 = unp2(acc[i][1]);
        float cv[4] = {c01.x, c01.y, c23.x, c23.y};
        #pragma unroll
        for (int j = 0; j < 4; j++)
            g_gi[base + (size_t)o * Bb + tb * 4 + j] = cv[j] + bv;
    }
}

// ------------------------- GCN aggregation (z & h gates) --------------------
__global__ void gcn_agg(const float* __restrict__ bz, const float* __restrict__ bh) {
    int t = blockIdx.x, b = blockIdx.y, c = threadIdx.x;
    size_t rowself = ((size_t)b * Nn + t) * Hh + c;
    float sn = g_selfnorm[t];
    float az = sn * g_xwz[rowself];
    float ah = sn * g_xwh[rowself];
    int e0 = g_rowptr[t], e1 = g_rowptr[t + 1];
    for (int e = e0; e < e1; e++) {
        int s = g_csr_src[e];
        float w = g_csr_norm[e];
        size_t ri = ((size_t)b * Nn + s) * Hh + c;
        az += w * g_xwz[ri];
        ah += w * g_xwh[ri];
    }
    g_cz[rowself] = az + bz[c];
    g_ch[rowself] = ah + bh[c];
}

// ------------------------- GRU layer 1 (producer) ----------------------------
// 64 CTAs = 8 clusters x 8. Cluster c owns batches [8c, 8c+8).
// CTA rank r: j-slice [32r,32r+32) of H, 96 Whh rows in smem.
// Thread: gate g, row jl, batch pair {bp, bp+4} (2 dots share the w row).
// Each step: publish h1 to global (stcg) + release flag (count-to-8).
__global__ void __launch_bounds__(384, 1) __cluster_dims__(8, 1, 1)
rec_l1(const float* __restrict__ Whh, const float* __restrict__ bhh) {
    extern __shared__ __align__(16) float sm[];
    float* Whs = sm;                          // 96 x 260
    float* hb0 = sm + 96 * 260;               // 8 x 260
    float* hb1 = hb0 + 8 * 260;               // 8 x 260
    float* ghs = hb1 + 8 * 260;               // 768

    int tid = threadIdx.x;
    uint32_t rank = ctarank();
    int cluster_id = blockIdx.x >> 3;
    int b0 = cluster_id * 8;

    int g  = tid >> 7;
    int rm = tid & 127;
    int jl = rm >> 2;
    int bp = rm & 3;                          // batches bp and bp+4
    int orow = g * Hh + rank * 32 + jl;

    for (int idx = tid; idx < 96 * 64; idx += 384) {
        int L = idx >> 6, k4 = idx & 63;
        int grow = (L >> 5) * Hh + rank * 32 + (L & 31);
        ((float4*)(Whs + L * 260))[k4] =
            ((const float4*)(Whh + (size_t)grow * Hh))[k4];
    }
    for (int idx = tid; idx < 8 * 260; idx += 384) hb0[idx] = 0.f;
    float bhv = bhh[orow];
    const ulonglong2* wr = (const ulonglong2*)(Whs + (g * 32 + jl) * 260);

    uint32_t hb0_u = smem_u32(hb0), hb1_u = smem_u32(hb1);

    size_t gi_a  = (size_t)orow * Bb + b0 + bp;
    size_t gi_b  = gi_a + 4;
    int cj = tid >> 3, cb = tid & 7;          // combine map (tid<256)
    size_t gi_nc = (size_t)(2 * Hh + rank * 32 + cj) * Bb + b0 + cb;

    float gva = (g < 2)     ? g_gi[gi_a] : 0.f;
    float gvb = (g < 2)     ? g_gi[gi_b] : 0.f;
    float gn  = (tid < 256) ? g_gi[gi_nc] : 0.f;

    __syncthreads();
    cluster_arrive_();
    cluster_wait_();

    for (int n = 0; n < Nn; n++) {
        const float* hread = (n & 1) ? hb1 : hb0;
        uint32_t hw_u = (n & 1) ? hb0_u : hb1_u;

        const ulonglong2* hA = (const ulonglong2*)(hread + bp * 260);
        const ulonglong2* hB = (const ulonglong2*)(hread + (bp + 4) * 260);
        uint64_t a0 = 0ull, a1 = 0ull, c0 = 0ull, c1 = 0ull;
        #pragma unroll 8
        for (int k4 = 0; k4 < 64; k4++) {
            ulonglong2 w = wr[k4];
            ulonglong2 x = hA[k4];
            ulonglong2 y = hB[k4];
            fma2(a0, w.x, x.x); fma2(a1, w.y, x.y);
            fma2(c0, w.x, y.x); fma2(c1, w.y, y.y);
        }
        float2 s0 = unp2(a0), s1 = unp2(a1), t0 = unp2(c0), t1 = unp2(c1);
        ghs[g * 256 + jl * 8 + bp]     = (s0.x + s0.y) + (s1.x + s1.y) + bhv + gva;
        ghs[g * 256 + jl * 8 + bp + 4] = (t0.x + t0.y) + (t1.x + t1.y) + bhv + gvb;
        __syncthreads();

        if (tid < 256) {
            float rr = sigf(ghs[tid]);
            float zz = sigf(ghs[256 + tid]);
            float nn = tanhf(gn + rr * ghs[512 + tid]);
            float hp = hread[cb * 260 + rank * 32 + cj];
            float hnew = (1.f - zz) * nn + zz * hp;
            uint32_t off = hw_u + (uint32_t)(cb * 260 + rank * 32 + cj) * 4u;
            #pragma unroll
            for (int p = 0; p < 8; p++) st_cluster_f32(off, p, hnew);
            __stcg(&g_h1[((size_t)n * Bb + b0 + cb) * Hh + rank * 32 + cj], hnew);
        }
        __syncthreads();
        if (tid == 0) {
            __threadfence();
            asm volatile("red.release.gpu.global.add.u32 [%0], %1;"
                         :: "l"(&g_flags[cluster_id * Nn + n]), "r"(1u) : "memory");
        }
        cluster_arrive_();

        int np = (n + 1 < Nn) ? n + 1 : n;
        size_t gib = (size_t)np * G3 * Bb;
        gva = (g < 2)     ? g_gi[gib + gi_a] : 0.f;
        gvb = (g < 2)     ? g_gi[gib + gi_b] : 0.f;
        gn  = (tid < 256) ? g_gi[gib + gi_nc] : 0.f;

        cluster_wait_();
    }
}

// ------------------------- GRU layer 2 (consumer) ----------------------------
// 64 CTAs = 8 clusters x 8. Same batch/j mapping. Holds BOTH Wih1 and Whh1
// slices in smem (230.8 KB). Per step: Whh1 dots first (local h2), then poll
// layer-1 flag, __ldcg h1(n), Wih1 dots, combine, DSMEM-broadcast h2.
__global__ void __launch_bounds__(384, 1) __cluster_dims__(8, 1, 1)
rec_l2(const float* __restrict__ Wih, const float* __restrict__ Whh,
       const float* __restrict__ bih, const float* __restrict__ bhh) {
    extern __shared__ __align__(16) float sm[];
    float* Wis = sm;                          // 96 x 260
    float* Whs = sm + 96 * 260;               // 96 x 260
    float* h1s = Whs + 96 * 260;              // 8 x 260
    float* hb0 = h1s + 8 * 260;               // 8 x 260
    float* hb1 = hb0 + 8 * 260;               // 8 x 260
    float* gI  = hb1 + 8 * 260;               // 768
    float* gH  = gI + 768;                    // 768

    int tid = threadIdx.x;
    uint32_t rank = ctarank();
    int cluster_id = blockIdx.x >> 3;
    int b0 = cluster_id * 8;

    int g  = tid >> 7;
    int rm = tid & 127;
    int jl = rm >> 2;
    int bp = rm & 3;
    int orow = g * Hh + rank * 32 + jl;

    for (int idx = tid; idx < 96 * 64; idx += 384) {
        int L = idx >> 6, k4 = idx & 63;
        int grow = (L >> 5) * Hh + rank * 32 + (L & 31);
        ((float4*)(Wis + L * 260))[k4] =
            ((const float4*)(Wih + (size_t)grow * Hh))[k4];
        ((float4*)(Whs + L * 260))[k4] =
            ((const float4*)(Whh + (size_t)grow * Hh))[k4];
    }
    for (int idx = tid; idx < 8 * 260; idx += 384) hb0[idx] = 0.f;
    float biv = bih[orow];
    float bhv = bhh[orow];
    const ulonglong2* wi = (const ulonglong2*)(Wis + (g * 32 + jl) * 260);
    const ulonglong2* wh = (const ulonglong2*)(Whs + (g * 32 + jl) * 260);

    uint32_t hb0_u = smem_u32(hb0), hb1_u = smem_u32(hb1);
    int cj = tid >> 3, cb = tid & 7;

    __syncthreads();
    cluster_arrive_();
    cluster_wait_();

    for (int n = 0; n < Nn; n++) {
        const float* hread = (n & 1) ? hb1 : hb0;
        uint32_t hw_u = (n & 1) ? hb0_u : hb1_u;

        // (1) hidden-path dots (no dependency on h1(n))
        {
            const ulonglong2* hA = (const ulonglong2*)(hread + bp * 260);
            const ulonglong2* hB = (const ulonglong2*)(hread + (bp + 4) * 260);
            uint64_t a0 = 0ull, a1 = 0ull, c0 = 0ull, c1 = 0ull;
            #pragma unroll 8
            for (int k4 = 0; k4 < 64; k4++) {
                ulonglong2 w = wh[k4];
                ulonglong2 x = hA[k4];
                ulonglong2 y = hB[k4];
                fma2(a0, w.x, x.x); fma2(a1, w.y, x.y);
                fma2(c0, w.x, y.x); fma2(c1, w.y, y.y);
            }
            float2 s0 = unp2(a0), s1 = unp2(a1), t0 = unp2(c0), t1 = unp2(c1);
            gH[g * 256 + jl * 8 + bp]     = (s0.x + s0.y) + (s1.x + s1.y) + bhv;
            gH[g * 256 + jl * 8 + bp + 4] = (t0.x + t0.y) + (t1.x + t1.y) + bhv;
        }

        // (2) wait for layer-1 step n
        if (tid == 0) {
            const unsigned* fp = &g_flags[cluster_id * Nn + n];
            unsigned v;
            while (true) {
                asm volatile("ld.acquire.gpu.global.u32 %0, [%1];"
                             : "=r"(v) : "l"(fp));
                if (v >= 8u) break;
                __nanosleep(32);
            }
        }
        __syncthreads();

        // (3) load h1(n) for our 8 batches (L2-only)
        for (int idx = tid; idx < 512; idx += 384) {
            int b = idx >> 6, k4 = idx & 63;
            float4 v = __ldcg(((const float4*)&g_h1[((size_t)n * Bb + b0 + b) * Hh]) + k4);
            *((float4*)(h1s + b * 260) + k4) = v;
        }
        __syncthreads();

        // (4) input-path dots over h1(n)
        {
            const ulonglong2* hA = (const ulonglong2*)(h1s + bp * 260);
            const ulonglong2* hB = (const ulonglong2*)(h1s + (bp + 4) * 260);
            uint64_t a0 = 0ull, a1 = 0ull, c0 = 0ull, c1 = 0ull;
            #pragma unroll 8
            for (int k4 = 0; k4 < 64; k4++) {
                ulonglong2 w = wi[k4];
                ulonglong2 x = hA[k4];
                ulonglong2 y = hB[k4];
                fma2(a0, w.x, x.x); fma2(a1, w.y, x.y);
                fma2(c0, w.x, y.x); fma2(c1, w.y, y.y);
            }
            float2 s0 = unp2(a0), s1 = unp2(a1), t0 = unp2(c0), t1 = unp2(c1);
            gI[g * 256 + jl * 8 + bp]     = (s0.x + s0.y) + (s1.x + s1.y) + biv;
            gI[g * 256 + jl * 8 + bp + 4] = (t0.x + t0.y) + (t1.x + t1.y) + biv;
        }
        __syncthreads();

        // (5) combine + broadcast new h2
        if (tid < 256) {
            float rr = sigf(gI[tid] + gH[tid]);
            float zz = sigf(gI[256 + tid] + gH[256 + tid]);
            float nn = tanhf(gI[512 + tid] + rr * gH[512 + tid]);
            float hp = hread[cb * 260 + rank * 32 + cj];
            float hnew = (1.f - zz) * nn + zz * hp;
            uint32_t off = hw_u + (uint32_t)(cb * 260 + rank * 32 + cj) * 4u;
            #pragma unroll
            for (int p = 0; p < 8; p++) st_cluster_f32(off, p, hnew);
            __stcg(&g_h2[((size_t)n * Bb + b0 + cb) * Hh + rank * 32 + cj], hnew);
        }
        cluster_arrive_();
        cluster_wait_();
    }
}

// ------------------------- fused epilogue -----------------------------------
__global__ void epilogue(const float* __restrict__ l1W, const float* __restrict__ l1b,
                         const float* __restrict__ l2W, const float* __restrict__ l2b,
                         const float* __restrict__ l3W, const float* __restrict__ l3b,
                         float* __restrict__ out) {
    __shared__ float red1[8], red2[8];
    __shared__ float s1s, s2s;
    int n = blockIdx.x, b = blockIdx.y, c = threadIdx.x;
    size_t i = ((size_t)b * Nn + n) * Hh + c;
    float z  = sigf(g_zlin[i]);
    float ht = tanhf(g_hlin[i]);
    float v1 = fmaxf((1.f - z) * ht, 0.f) * l1W[c];
    float v2 = g_h2[((size_t)n * Bb + b) * Hh + c] * l2W[c];
    #pragma unroll
    for (int o = 16; o; o >>= 1) {
        v1 += __shfl_down_sync(0xffffffffu, v1, o);
        v2 += __shfl_down_sync(0xffffffffu, v2, o);
    }
    if ((c & 31) == 0) { red1[c >> 5] = v1; red2[c >> 5] = v2; }
    __syncthreads();
    if (c == 0) {
        float a = 0.f, bs = 0.f;
        #pragma unroll
        for (int k = 0; k < 8; k++) { a += red1[k]; bs += red2[k]; }
        s1s = a + l1b[0];
        s2s = bs + l2b[0];
    }
    __syncthreads();
    if (c < OUTd)
        out[((size_t)b * Nn + n) * OUTd + c] =
            s2s * l3W[c] + s1s * l3W[OUTd + c] + l3b[c];
}

// ------------------------- launch -------------------------------------------
extern "C" void kernel_launch(void* const* d_in, const int* in_sizes, int n_in,
                              void* d_out, int out_size) {
    const float* x    = (const float*)d_in[0];
    const int*   ei   = (const int*)d_in[1];
    const float* ew   = (const float*)d_in[2];
    const float* Wz   = (const float*)d_in[3];
    const float* bz   = (const float*)d_in[4];
    const float* lzW  = (const float*)d_in[5];
    const float* lzb  = (const float*)d_in[6];
    // d_in[7..10] (R gate) algebraically dead since H0 = 0
    const float* Wh   = (const float*)d_in[11];
    const float* bh   = (const float*)d_in[12];
    const float* lhW  = (const float*)d_in[13];
    const float* lhb  = (const float*)d_in[14];
    const float* Wih0 = (const float*)d_in[15];
    const float* Whh0 = (const float*)d_in[16];
    const float* bih0 = (const float*)d_in[17];
    const float* bhh0 = (const float*)d_in[18];
    const float* Wih1 = (const float*)d_in[19];
    const float* Whh1 = (const float*)d_in[20];
    const float* bih1 = (const float*)d_in[21];
    const float* bhh1 = (const float*)d_in[22];
    const float* l1W  = (const float*)d_in[23];
    const float* l1b  = (const float*)d_in[24];
    const float* l2W  = (const float*)d_in[25];
    const float* l2b  = (const float*)d_in[26];
    const float* l3W  = (const float*)d_in[27];
    const float* l3b  = (const float*)d_in[28];
    float* out = (float*)d_out;

    float *xwz, *xwh, *cz, *ch, *zlin, *hlin;
    unsigned* flags;
    cudaGetSymbolAddress((void**)&xwz,   g_xwz);
    cudaGetSymbolAddress((void**)&xwh,   g_xwh);
    cudaGetSymbolAddress((void**)&cz,    g_cz);
    cudaGetSymbolAddress((void**)&ch,    g_ch);
    cudaGetSymbolAddress((void**)&zlin,  g_zlin);
    cudaGetSymbolAddress((void**)&hlin,  g_hlin);
    cudaGetSymbolAddress((void**)&flags, g_flags);

    const int SM1 = (96 * 260 + 16 * 260 + 768) * 4;            // 119,552 B
    const int SM2 = (192 * 260 + 24 * 260 + 1536) * 4;          // 230,784 B
    cudaFuncSetAttribute(rec_l1, cudaFuncAttributeMaxDynamicSharedMemorySize, SM1);
    cudaFuncSetAttribute(rec_l2, cudaFuncAttributeMaxDynamicSharedMemorySize, SM2);

    static cudaStream_t s2 = nullptr, s3 = nullptr;
    static cudaEvent_t evFork = nullptr, evJoin = nullptr, evL2 = nullptr;
    if (s2 == nullptr) {
        cudaStreamCreateWithFlags(&s2, cudaStreamNonBlocking);
        cudaStreamCreateWithFlags(&s3, cudaStreamNonBlocking);
        cudaEventCreateWithFlags(&evFork, cudaEventDisableTiming);
        cudaEventCreateWithFlags(&evJoin, cudaEventDisableTiming);
        cudaEventCreateWithFlags(&evL2,   cudaEventDisableTiming);
    }

    // clear the layer1->layer2 flags for this call
    cudaMemsetAsync(flags, 0, 8 * Nn * sizeof(unsigned), 0);
    cudaEventRecord(evFork, 0);
    cudaStreamWaitEvent(s2, evFork, 0);
    cudaStreamWaitEvent(s3, evFork, 0);

    dim3 g1(BN / 64, Hh / 64);
    dim3 g2(Nn, Bb);
    dim3 g3(Nn, G3 / 64);

    // (harness launches 2 kernels before ours; ncu -s 5 profiles our #3)
    gi_gemm<<<g3, 256>>>(x, Nn * CINc, CINc, Wih0, bih0, CINc);          // our 0
    prep_init<<<1, 512, 0, s2>>>();                                      // our 1
    prep_count<<<(Ee + 255) / 256, 256, 0, s2>>>(ei, ew);                // our 2
    rec_l1<<<64, 384, SM1>>>(Whh0, bhh0);                                // our 3
    rec_l2<<<64, 384, SM2, s3>>>(Wih1, Whh1, bih1, bhh1);                // our 4
    cudaEventRecord(evL2, s3);
    prep_scan<<<1, Nn, 0, s2>>>();
    prep_fill<<<(Ee + 255) / 256, 256, 0, s2>>>(ei, ew);
    sgemm64<<<g1, 256, 0, s2>>>(x, Wz, nullptr, xwz, BN, CINc, Hh);
    sgemm64<<<g1, 256, 0, s2>>>(x, Wh, nullptr, xwh, BN, CINc, Hh);
    gcn_agg<<<g2, 256, 0, s2>>>(bz, bh);
    sgemm64<<<g1, 256, 0, s2>>>(cz, lzW, lzb, zlin, BN, Hh, Hh);
    sgemm64<<<g1, 256, 0, s2>>>(ch, lhW, lhb, hlin, BN, Hh, Hh);
    cudaEventRecord(evJoin, s2);

    cudaStreamWaitEvent(0, evL2, 0);
    cudaStreamWaitEvent(0, evJoin, 0);
    epilogue<<<g2, 256>>>(l1W, l1b, l2W, l2b, l3W, l3b, out);
}